// round 14
// baseline (speedup 1.0000x reference)
#include <cuda_runtime.h>
#include <math.h>

#define HH 512
#define WW 512
#define BB 32
#define CCH 3
#define NCHUNK 8
#define CROWS 64          // HH / NCHUNK
#define R3ROWS 8
#define TWO_PI 6.283185307179586f

typedef unsigned long long u64;

__device__ __forceinline__ u64 pk(float lo, float hi) {
    u64 r; asm("mov.b64 %0,{%1,%2};" : "=l"(r) : "f"(lo), "f"(hi)); return r;
}
__device__ __forceinline__ float2 upk(u64 v) {
    float2 f; asm("mov.b64 {%0,%1},%2;" : "=f"(f.x), "=f"(f.y) : "l"(v)); return f;
}
__device__ __forceinline__ u64 fma2_(u64 a, u64 b, u64 c) {
    u64 d; asm("fma.rn.f32x2 %0,%1,%2,%3;" : "=l"(d) : "l"(a), "l"(b), "l"(c)); return d;
}
__device__ __forceinline__ u64 add2_(u64 a, u64 b) {
    u64 d; asm("add.rn.f32x2 %0,%1,%2;" : "=l"(d) : "l"(a), "l"(b)); return d;
}

// Scratch (device globals — no allocation allowed)
// g_cols: per (bc,chunk), 7 coefficient planes of 512 w's:
//   c=0: S0 ; c=1,2: C1 re,im ; c=3,4: C2 re,im ; c=5,6: C3 re,im
__device__ float  g_cols[BB * CCH * NCHUNK * 7 * WW];
__device__ float  g_proj[BB * CCH * 7 * 7];  // [bc][plane][R0,R1,I1,R2,I2,R3,I3]
__device__ float4 g_d4[BB * CCH * HH * 3];   // [bc][h][12 floats]: |z|^2 autocorr coeffs

// ---------------------------------------------------------------------------
// Kernel 1 (identical to R13, measured 25.0us): column sums only.
// Thread = float4 of w. Block 128, grid (8, 96) = 768 blocks.
// ---------------------------------------------------------------------------
__global__ __launch_bounds__(128) void k1_coldft(const float* __restrict__ x) {
    const int chunk = blockIdx.x;
    const int bc    = blockIdx.y;
    const int t     = threadIdx.x;
    const int h0    = chunk * CROWS;

    __shared__ __align__(16) u64 twc[CROWS][3], tws[CROWS][3];

    for (int i = t; i < CROWS * 3; i += 128) {
        int hl = i / 3, K = (i % 3) + 1;
        float a = TWO_PI * (float)(h0 + hl) * (1.0f / (float)HH) * (float)K;
        float s, c; __sincosf(a, &s, &c);
        twc[hl][K - 1] = pk(c, c);
        tws[hl][K - 1] = pk(s, s);
    }
    __syncthreads();

    u64 S0[2] = {0ULL, 0ULL};
    u64 Cr[3][2], Ci[3][2];
#pragma unroll
    for (int K = 0; K < 3; K++) { Cr[K][0] = Cr[K][1] = 0ULL; Ci[K][0] = Ci[K][1] = 0ULL; }

    const float4* xp = (const float4*)(x + (size_t)bc * HH * WW + (size_t)h0 * WW) + t;
#pragma unroll 8
    for (int hl = 0; hl < CROWS; ++hl) {
        float4 v = __ldg(xp + (size_t)hl * (WW / 4));
        u64 v01 = pk(v.x, v.y), v23 = pk(v.z, v.w);
        S0[0] = add2_(S0[0], v01);
        S0[1] = add2_(S0[1], v23);
#pragma unroll
        for (int K = 0; K < 3; K++) {
            u64 cc = twc[hl][K], ss = tws[hl][K];
            Cr[K][0] = fma2_(v01, cc, Cr[K][0]);
            Ci[K][0] = fma2_(v01, ss, Ci[K][0]);
            Cr[K][1] = fma2_(v23, cc, Cr[K][1]);
            Ci[K][1] = fma2_(v23, ss, Ci[K][1]);
        }
    }

    float4* gp = (float4*)(g_cols + ((size_t)(bc * NCHUNK + chunk) * 7) * WW) + t;
    {
        float2 a0 = upk(S0[0]), a1 = upk(S0[1]);
        gp[0] = make_float4(a0.x, a0.y, a1.x, a1.y);
    }
#pragma unroll
    for (int K = 0; K < 3; K++) {
        float2 r0 = upk(Cr[K][0]), r1 = upk(Cr[K][1]);
        float2 i0 = upk(Ci[K][0]), i1 = upk(Ci[K][1]);
        gp[(1 + 2 * K) * (WW / 4)] = make_float4(r0.x, r0.y, r1.x, r1.y);
        gp[(2 + 2 * K) * (WW / 4)] = make_float4(i0.x, i0.y, i1.x, i1.y);
    }
}

// ---------------------------------------------------------------------------
// Kernel 2a: per (bc, plane c): sum 8 chunk partials, project the REAL plane
// onto cos/sin(n phi) for n=0..3 (7 real reductions). grid (96, 7), block 512.
// ---------------------------------------------------------------------------
__global__ __launch_bounds__(512) void k2a_project() {
    const int bc = blockIdx.x;
    const int c  = blockIdx.y;
    const int t  = threadIdx.x;   // w
    const int wid = t >> 5, lid = t & 31;

    __shared__ float part[16][7];

    const float* gp = g_cols + ((size_t)bc * NCHUNK * 7 + c) * WW + t;
    float v = 0.f;
#pragma unroll
    for (int ch = 0; ch < NCHUNK; ch++) v += gp[(size_t)ch * 7 * WW];

    float phi = TWO_PI * (float)t * (1.0f / (float)WW);
    float c1, s1; __sincosf(phi, &s1, &c1);
    float c2 = c1 * c1 - s1 * s1, s2 = 2.f * c1 * s1;
    float c3 = c2 * c1 - s2 * s1, s3 = c2 * s1 + s2 * c1;

    float p[7] = { v, v * c1, v * s1, v * c2, v * s2, v * c3, v * s3 };
#pragma unroll
    for (int off = 16; off >= 1; off >>= 1)
#pragma unroll
        for (int j = 0; j < 7; j++) p[j] += __shfl_xor_sync(0xFFFFFFFFu, p[j], off);
    if (lid == 0)
#pragma unroll
        for (int j = 0; j < 7; j++) part[wid][j] = p[j];
    __syncthreads();

    if (t < 7) {
        float s = 0.f;
#pragma unroll
        for (int q = 0; q < 16; q++) s += part[q][t];
        g_proj[(bc * 7 + c) * 7 + t] = s;
    }
}

// ---------------------------------------------------------------------------
// Kernel 2b: assemble F[6][6] from the 49 projections, then phase B:
// gg[h][k] = sum_u F[u][k] D_u(h); autocorr coeffs -> g_d4. grid 96, block 512.
// ---------------------------------------------------------------------------
__device__ __forceinline__ void proj_pk(const float* A, int c, int k, float& re, float& im) {
    // P_c[k] = sum_w plane_c(w) e^{i(3-k)phi_w}; A row = [R0,R1,I1,R2,I2,R3,I3]
    int n = 3 - k;
    const float* a = A + c * 7;
    if (n > 0)      { re = a[2 * n - 1]; im = a[2 * n]; }
    else if (n == 0){ re = a[0];         im = 0.f; }
    else            { re = a[-2 * n - 1]; im = -a[-2 * n]; }
}

__global__ __launch_bounds__(512) void k2b_reduce() {
    const int bc = blockIdx.x;
    const int t  = threadIdx.x;

    __shared__ float A[49];
    __shared__ float F[72];

    if (t < 49) A[t] = g_proj[bc * 49 + t];
    __syncthreads();

    if (t < 36) {
        const float inv = 1.0f / ((float)HH * (float)WW);
        int u = t / 6, k = t % 6;
        float Fre, Fim;
        if (u == 3) {
            proj_pk(A, 0, k, Fre, Fim);
        } else if (u < 3) {
            int K = 3 - u;
            float pr_re, pr_im, pi_re, pi_im;
            proj_pk(A, 2 * K - 1, k, pr_re, pr_im);
            proj_pk(A, 2 * K,     k, pi_re, pi_im);
            Fre = pr_re - pi_im;     // F = Pr + i*Pi
            Fim = pr_im + pi_re;
        } else {
            int K = u - 3;
            float pr_re, pr_im, pi_re, pi_im;
            proj_pk(A, 2 * K - 1, k, pr_re, pr_im);
            proj_pk(A, 2 * K,     k, pi_re, pi_im);
            Fre = pr_re + pi_im;     // F = Pr - i*Pi
            Fim = pr_im - pi_re;
        }
        F[2 * t]     = Fre * inv;
        F[2 * t + 1] = Fim * inv;
    }
    __syncthreads();

    // phase B: t = h
    {
        float psi = TWO_PI * (float)t * (1.0f / (float)HH);
        float d1c, d1s; __sincosf(psi, &d1s, &d1c);
        float d2c = d1c * d1c - d1s * d1s, d2s = 2.f * d1c * d1s;
        float d3c = d2c * d1c - d2s * d1s, d3s = d2c * d1s + d2s * d1c;
        float Dc[6] = { d3c,  d2c,  d1c,  1.f, d1c, d2c };
        float Ds[6] = { -d3s, -d2s, -d1s, 0.f, d1s, d2s };

        float gr[6], gi[6];
#pragma unroll
        for (int k = 0; k < 6; k++) {
            float r = 0.f, im = 0.f;
#pragma unroll
            for (int u = 0; u < 6; u++) {
                float Fr = F[(u * 6 + k) * 2 + 0];
                float Fi = F[(u * 6 + k) * 2 + 1];
                r  += Fr * Dc[u] - Fi * Ds[u];
                im += Fr * Ds[u] + Fi * Dc[u];
            }
            gr[k] = r; gi[k] = im;
        }

        float d[12];
        {
            float c0 = 0.f;
#pragma unroll
            for (int k = 0; k < 6; k++) c0 = fmaf(gr[k], gr[k], fmaf(gi[k], gi[k], c0));
            d[0] = c0;
#pragma unroll
            for (int m = 1; m <= 5; m++) {
                float re = 0.f, im = 0.f;
#pragma unroll
                for (int k = m; k < 6; k++) {
                    re = fmaf(gr[k], gr[k - m], fmaf(gi[k], gi[k - m], re));
                    im = fmaf(gi[k], gr[k - m], fmaf(-gr[k], gi[k - m], im));
                }
                d[2 * m - 1] = 2.f * re;
                d[2 * m]     = -2.f * im;
            }
            d[11] = 0.f;
        }

        float4* dp = g_d4 + ((size_t)bc * HH + t) * 3;
        dp[0] = make_float4(d[0], d[1], d[2],  d[3]);
        dp[1] = make_float4(d[4], d[5], d[6],  d[7]);
        dp[2] = make_float4(d[8], d[9], d[10], d[11]);
    }
}

// ---------------------------------------------------------------------------
// Kernel 3: |z| via autocorr + MLP + residual + clip. 4 pixels per thread
// (float4 stores); coefficient LDS + loop overhead amortized 2x vs R12.
// grid (H/8, B) = (64, 32), block 128.
// ---------------------------------------------------------------------------
__global__ __launch_bounds__(128, 3) void k3_final(const float* __restrict__ w1,
                                                   const float* __restrict__ b1,
                                                   const float* __restrict__ w2,
                                                   const float* __restrict__ b2,
                                                   float* __restrict__ out) {
    const int b  = blockIdx.y;
    const int h0 = blockIdx.x * R3ROWS;
    const int t  = threadIdx.x;   // 4 pixels: w = 4t .. 4t+3

    __shared__ __align__(16) float sd[R3ROWS * 3 * 12];  // [r][ch][12]
    __shared__ float wt[64];

    if (t < 72) {   // 72 float4 = 288 floats
        int r  = t / 9;
        int ch = (t % 9) / 3;
        int q  = t % 3;
        ((float4*)sd)[t] = g_d4[(((size_t)(b * 3 + ch) * HH) + (h0 + r)) * 3 + q];
    }
    for (int i = t; i < 59; i += 128)
        wt[i] = (i < 24) ? w1[i] : (i < 32) ? b1[i - 24] : (i < 56) ? w2[i - 32] : b2[i - 56];
    __syncthreads();

    // hidden-layer weights in registers; output-layer read from smem (broadcast)
    float W1r[8][3], B1r[8];
#pragma unroll
    for (int j = 0; j < 8; j++) {
#pragma unroll
        for (int cc = 0; cc < 3; cc++) W1r[j][cc] = wt[j * 3 + cc];
        B1r[j] = wt[24 + j];
    }

    // cos/sin basis m=1..5 for 4 pixels (Chebyshev, hoisted)
    float cb[4][6], sb[4][6];
#pragma unroll
    for (int p = 0; p < 4; p++) {
        __sincosf(TWO_PI * (float)(4 * t + p) * (1.0f / (float)WW), &sb[p][1], &cb[p][1]);
        float kk = 2.f * cb[p][1];
        cb[p][0] = 1.f; sb[p][0] = 0.f;
#pragma unroll
        for (int m = 2; m <= 5; m++) {
            cb[p][m] = fmaf(kk, cb[p][m - 1], -cb[p][m - 2]);
            sb[p][m] = fmaf(kk, sb[p][m - 1], -sb[p][m - 2]);
        }
    }

#pragma unroll
    for (int r = 0; r < R3ROWS; ++r) {
        float lp[3][4];
#pragma unroll
        for (int ch = 0; ch < 3; ch++) {
            const float* dd = &sd[(r * 3 + ch) * 12];
            float acc[4];
            float d0 = dd[0];
#pragma unroll
            for (int p = 0; p < 4; p++) acc[p] = d0;
#pragma unroll
            for (int m = 1; m <= 5; m++) {
                float dre = dd[2 * m - 1], dim = dd[2 * m];
#pragma unroll
                for (int p = 0; p < 4; p++)
                    acc[p] = fmaf(dre, cb[p][m], fmaf(dim, sb[p][m], acc[p]));
            }
#pragma unroll
            for (int p = 0; p < 4; p++) {
                float sa = fmaxf(acc[p], 1e-30f);
                lp[ch][p] = sa * __frsqrt_rn(sa);
            }
        }

        float hv[8][4];
#pragma unroll
        for (int j = 0; j < 8; j++) {
#pragma unroll
            for (int p = 0; p < 4; p++) {
                float a = B1r[j];
                a = fmaf(W1r[j][0], lp[0][p], a);
                a = fmaf(W1r[j][1], lp[1][p], a);
                a = fmaf(W1r[j][2], lp[2][p], a);
                hv[j][p] = fmaxf(a, 0.f);
            }
        }

#pragma unroll
        for (int ch = 0; ch < 3; ch++) {
            float y[4];
            float bb = wt[56 + ch];
#pragma unroll
            for (int p = 0; p < 4; p++) y[p] = bb + lp[ch][p];
#pragma unroll
            for (int j = 0; j < 8; j++) {
                float wv = wt[32 + ch * 8 + j];
#pragma unroll
                for (int p = 0; p < 4; p++) y[p] = fmaf(wv, hv[j][p], y[p]);
            }
            float4 yo;
            yo.x = __saturatef(y[0]); yo.y = __saturatef(y[1]);
            yo.z = __saturatef(y[2]); yo.w = __saturatef(y[3]);
            float4* orow = (float4*)(out + (((size_t)(b * 3 + ch) * HH) + (h0 + r)) * WW);
            orow[t] = yo;
        }
    }
}

// ---------------------------------------------------------------------------
extern "C" void kernel_launch(void* const* d_in, const int* in_sizes, int n_in,
                              void* d_out, int out_size) {
    const float* x  = (const float*)d_in[0];
    const float* w1 = (const float*)d_in[1];
    const float* b1 = (const float*)d_in[2];
    const float* w2 = (const float*)d_in[3];
    const float* b2 = (const float*)d_in[4];
    float* out = (float*)d_out;

    k1_coldft<<<dim3(NCHUNK, BB * CCH), 128>>>(x);
    k2a_project<<<dim3(BB * CCH, 7), 512>>>();
    k2b_reduce<<<BB * CCH, 512>>>();
    k3_final<<<dim3(HH / R3ROWS, BB), 128>>>(w1, b1, w2, b2, out);
}

// round 15
// speedup vs baseline: 1.0313x; 1.0313x over previous
#include <cuda_runtime.h>
#include <math.h>

#define HH 512
#define WW 512
#define BB 32
#define CCH 3
#define NCHUNK 16
#define CROWS 32          // HH / NCHUNK
#define R3ROWS 8
#define TWO_PI 6.283185307179586f

typedef unsigned long long u64;

__device__ __forceinline__ u64 pk(float lo, float hi) {
    u64 r; asm("mov.b64 %0,{%1,%2};" : "=l"(r) : "f"(lo), "f"(hi)); return r;
}
__device__ __forceinline__ float2 upk(u64 v) {
    float2 f; asm("mov.b64 {%0,%1},%2;" : "=f"(f.x), "=f"(f.y) : "l"(v)); return f;
}
__device__ __forceinline__ u64 fma2_(u64 a, u64 b, u64 c) {
    u64 d; asm("fma.rn.f32x2 %0,%1,%2,%3;" : "=l"(d) : "l"(a), "l"(b), "l"(c)); return d;
}
__device__ __forceinline__ u64 add2_(u64 a, u64 b) {
    u64 d; asm("add.rn.f32x2 %0,%1,%2;" : "=l"(d) : "l"(a), "l"(b)); return d;
}

// Scratch (device globals — no allocation allowed)
__device__ float  g_cols[BB * CCH * NCHUNK * 7 * WW];
__device__ float  g_proj[BB * CCH * 7 * 7];  // [bc][plane][R0,R1,I1,R2,I2,R3,I3]
__device__ float4 g_d4[BB * CCH * HH * 3];   // [bc][h][12 floats]: autocorr coeffs

// ---------------------------------------------------------------------------
// Kernel 1: column sums only, store-only epilogue. 32-row tiles for occupancy.
// Thread = float4 of w. Block 128, grid (16, 96) = 1536 blocks.
// ---------------------------------------------------------------------------
__global__ __launch_bounds__(128) void k1_coldft(const float* __restrict__ x) {
    const int chunk = blockIdx.x;
    const int bc    = blockIdx.y;
    const int t     = threadIdx.x;
    const int h0    = chunk * CROWS;

    __shared__ __align__(16) u64 twc[CROWS][3], tws[CROWS][3];

    if (t < CROWS * 3) {
        int hl = t / 3, K = (t % 3) + 1;
        float a = TWO_PI * (float)(h0 + hl) * (1.0f / (float)HH) * (float)K;
        float s, c; __sincosf(a, &s, &c);
        twc[hl][K - 1] = pk(c, c);
        tws[hl][K - 1] = pk(s, s);
    }
    __syncthreads();

    u64 S0[2] = {0ULL, 0ULL};
    u64 Cr[3][2], Ci[3][2];
#pragma unroll
    for (int K = 0; K < 3; K++) { Cr[K][0] = Cr[K][1] = 0ULL; Ci[K][0] = Ci[K][1] = 0ULL; }

    const float4* xp = (const float4*)(x + (size_t)bc * HH * WW + (size_t)h0 * WW) + t;
#pragma unroll 8
    for (int hl = 0; hl < CROWS; ++hl) {
        float4 v = __ldg(xp + (size_t)hl * (WW / 4));
        u64 v01 = pk(v.x, v.y), v23 = pk(v.z, v.w);
        S0[0] = add2_(S0[0], v01);
        S0[1] = add2_(S0[1], v23);
#pragma unroll
        for (int K = 0; K < 3; K++) {
            u64 cc = twc[hl][K], ss = tws[hl][K];
            Cr[K][0] = fma2_(v01, cc, Cr[K][0]);
            Ci[K][0] = fma2_(v01, ss, Ci[K][0]);
            Cr[K][1] = fma2_(v23, cc, Cr[K][1]);
            Ci[K][1] = fma2_(v23, ss, Ci[K][1]);
        }
    }

    float4* gp = (float4*)(g_cols + ((size_t)(bc * NCHUNK + chunk) * 7) * WW) + t;
    {
        float2 a0 = upk(S0[0]), a1 = upk(S0[1]);
        gp[0] = make_float4(a0.x, a0.y, a1.x, a1.y);
    }
#pragma unroll
    for (int K = 0; K < 3; K++) {
        float2 r0 = upk(Cr[K][0]), r1 = upk(Cr[K][1]);
        float2 i0 = upk(Ci[K][0]), i1 = upk(Ci[K][1]);
        gp[(1 + 2 * K) * (WW / 4)] = make_float4(r0.x, r0.y, r1.x, r1.y);
        gp[(2 + 2 * K) * (WW / 4)] = make_float4(i0.x, i0.y, i1.x, i1.y);
    }
}

// ---------------------------------------------------------------------------
// Kernel 2a: per (bc, plane c): sum 16 chunk partials, project onto
// cos/sin(n phi), n=0..3 (7 real reductions). grid (96, 7), block 512.
// ---------------------------------------------------------------------------
__global__ __launch_bounds__(512) void k2a_project() {
    const int bc = blockIdx.x;
    const int c  = blockIdx.y;
    const int t  = threadIdx.x;   // w
    const int wid = t >> 5, lid = t & 31;

    __shared__ float part[16][7];

    const float* gp = g_cols + ((size_t)bc * NCHUNK * 7 + c) * WW + t;
    float v = 0.f;
#pragma unroll
    for (int ch = 0; ch < NCHUNK; ch++) v += gp[(size_t)ch * 7 * WW];

    float phi = TWO_PI * (float)t * (1.0f / (float)WW);
    float c1, s1; __sincosf(phi, &s1, &c1);
    float c2 = c1 * c1 - s1 * s1, s2 = 2.f * c1 * s1;
    float c3 = c2 * c1 - s2 * s1, s3 = c2 * s1 + s2 * c1;

    float p[7] = { v, v * c1, v * s1, v * c2, v * s2, v * c3, v * s3 };
#pragma unroll
    for (int off = 16; off >= 1; off >>= 1)
#pragma unroll
        for (int j = 0; j < 7; j++) p[j] += __shfl_xor_sync(0xFFFFFFFFu, p[j], off);
    if (lid == 0)
#pragma unroll
        for (int j = 0; j < 7; j++) part[wid][j] = p[j];
    __syncthreads();

    if (t < 7) {
        float s = 0.f;
#pragma unroll
        for (int q = 0; q < 16; q++) s += part[q][t];
        g_proj[(bc * 7 + c) * 7 + t] = s;
    }
}

// ---------------------------------------------------------------------------
// Kernel 2b: assemble F[6][6] from projections; phase B: gg + autocorr -> g_d4.
// grid 96, block 512.
// ---------------------------------------------------------------------------
__device__ __forceinline__ void proj_pk(const float* A, int c, int k, float& re, float& im) {
    int n = 3 - k;
    const float* a = A + c * 7;
    if (n > 0)      { re = a[2 * n - 1]; im = a[2 * n]; }
    else if (n == 0){ re = a[0];         im = 0.f; }
    else            { re = a[-2 * n - 1]; im = -a[-2 * n]; }
}

__global__ __launch_bounds__(512) void k2b_reduce() {
    const int bc = blockIdx.x;
    const int t  = threadIdx.x;

    __shared__ float A[49];
    __shared__ float F[72];

    if (t < 49) A[t] = g_proj[bc * 49 + t];
    __syncthreads();

    if (t < 36) {
        const float inv = 1.0f / ((float)HH * (float)WW);
        int u = t / 6, k = t % 6;
        float Fre, Fim;
        if (u == 3) {
            proj_pk(A, 0, k, Fre, Fim);
        } else if (u < 3) {
            int K = 3 - u;
            float pr_re, pr_im, pi_re, pi_im;
            proj_pk(A, 2 * K - 1, k, pr_re, pr_im);
            proj_pk(A, 2 * K,     k, pi_re, pi_im);
            Fre = pr_re - pi_im;
            Fim = pr_im + pi_re;
        } else {
            int K = u - 3;
            float pr_re, pr_im, pi_re, pi_im;
            proj_pk(A, 2 * K - 1, k, pr_re, pr_im);
            proj_pk(A, 2 * K,     k, pi_re, pi_im);
            Fre = pr_re + pi_im;
            Fim = pr_im - pi_re;
        }
        F[2 * t]     = Fre * inv;
        F[2 * t + 1] = Fim * inv;
    }
    __syncthreads();

    {
        float psi = TWO_PI * (float)t * (1.0f / (float)HH);
        float d1c, d1s; __sincosf(psi, &d1s, &d1c);
        float d2c = d1c * d1c - d1s * d1s, d2s = 2.f * d1c * d1s;
        float d3c = d2c * d1c - d2s * d1s, d3s = d2c * d1s + d2s * d1c;
        float Dc[6] = { d3c,  d2c,  d1c,  1.f, d1c, d2c };
        float Ds[6] = { -d3s, -d2s, -d1s, 0.f, d1s, d2s };

        float gr[6], gi[6];
#pragma unroll
        for (int k = 0; k < 6; k++) {
            float r = 0.f, im = 0.f;
#pragma unroll
            for (int u = 0; u < 6; u++) {
                float Fr = F[(u * 6 + k) * 2 + 0];
                float Fi = F[(u * 6 + k) * 2 + 1];
                r  += Fr * Dc[u] - Fi * Ds[u];
                im += Fr * Ds[u] + Fi * Dc[u];
            }
            gr[k] = r; gi[k] = im;
        }

        float d[12];
        {
            float c0 = 0.f;
#pragma unroll
            for (int k = 0; k < 6; k++) c0 = fmaf(gr[k], gr[k], fmaf(gi[k], gi[k], c0));
            d[0] = c0;
#pragma unroll
            for (int m = 1; m <= 5; m++) {
                float re = 0.f, im = 0.f;
#pragma unroll
                for (int k = m; k < 6; k++) {
                    re = fmaf(gr[k], gr[k - m], fmaf(gi[k], gi[k - m], re));
                    im = fmaf(gi[k], gr[k - m], fmaf(-gr[k], gi[k - m], im));
                }
                d[2 * m - 1] = 2.f * re;
                d[2 * m]     = -2.f * im;
            }
            d[11] = 0.f;
        }

        float4* dp = g_d4 + ((size_t)bc * HH + t) * 3;
        dp[0] = make_float4(d[0], d[1], d[2],  d[3]);
        dp[1] = make_float4(d[4], d[5], d[6],  d[7]);
        dp[2] = make_float4(d[8], d[9], d[10], d[11]);
    }
}

// ---------------------------------------------------------------------------
// Kernel 3: autocorr recon + MLP + residual + clip. 2 pixels per thread.
// Output accumulation interleaved into the hidden-unit loop (no hv arrays).
// __launch_bounds__(256,3) caps regs at 85 -> 24 warps/SM.
// grid (H/8, B) = (64, 32), block 256.
// ---------------------------------------------------------------------------
__global__ __launch_bounds__(256, 3) void k3_final(const float* __restrict__ w1,
                                                   const float* __restrict__ b1,
                                                   const float* __restrict__ w2,
                                                   const float* __restrict__ b2,
                                                   float* __restrict__ out) {
    const int b  = blockIdx.y;
    const int h0 = blockIdx.x * R3ROWS;
    const int t  = threadIdx.x;   // pixel pair (2t, 2t+1)

    __shared__ __align__(16) float sd[R3ROWS * 3 * 12];  // [r][ch][12]
    __shared__ float wt[64];

    if (t < 72) {
        int r  = t / 9;
        int ch = (t % 9) / 3;
        int q  = t % 3;
        ((float4*)sd)[t] = g_d4[(((size_t)(b * 3 + ch) * HH) + (h0 + r)) * 3 + q];
    } else if (t >= 128 && t < 128 + 24) {
        wt[t - 128] = w1[t - 128];
    } else if (t >= 128 + 24 && t < 128 + 32) {
        wt[t - 128] = b1[t - 152];
    } else if (t >= 128 + 32 && t < 128 + 56) {
        wt[t - 128] = w2[t - 160];
    } else if (t >= 128 + 56 && t < 128 + 59) {
        wt[t - 128] = b2[t - 184];
    }
    __syncthreads();

    float W1r[8][3], B1r[8], W2r[3][8], B2r[3];
#pragma unroll
    for (int j = 0; j < 8; j++) {
#pragma unroll
        for (int cc = 0; cc < 3; cc++) W1r[j][cc] = wt[j * 3 + cc];
        B1r[j] = wt[24 + j];
    }
#pragma unroll
    for (int cc = 0; cc < 3; cc++) {
#pragma unroll
        for (int j = 0; j < 8; j++) W2r[cc][j] = wt[32 + cc * 8 + j];
        B2r[cc] = wt[56 + cc];
    }

    // cos/sin basis m=1..5, both pixels (Chebyshev, hoisted)
    float cA[6], sA[6], cB[6], sB[6];
    {
        const int w0 = 2 * t;
        __sincosf(TWO_PI * (float)w0       * (1.0f / (float)WW), &sA[1], &cA[1]);
        __sincosf(TWO_PI * (float)(w0 + 1) * (1.0f / (float)WW), &sB[1], &cB[1]);
        float kA = 2.f * cA[1], kB = 2.f * cB[1];
        cA[0] = 1.f; sA[0] = 0.f; cB[0] = 1.f; sB[0] = 0.f;
#pragma unroll
        for (int m = 2; m <= 5; m++) {
            cA[m] = fmaf(kA, cA[m - 1], -cA[m - 2]);
            sA[m] = fmaf(kA, sA[m - 1], -sA[m - 2]);
            cB[m] = fmaf(kB, cB[m - 1], -cB[m - 2]);
            sB[m] = fmaf(kB, sB[m - 1], -sB[m - 2]);
        }
    }

#pragma unroll
    for (int r = 0; r < R3ROWS; ++r) {
        float lpA[3], lpB[3];
#pragma unroll
        for (int ch = 0; ch < 3; ch++) {
            const float* dd = &sd[(r * 3 + ch) * 12];
            float sa = dd[0], sb = dd[0];
#pragma unroll
            for (int m = 1; m <= 5; m++) {
                float dre = dd[2 * m - 1], dim = dd[2 * m];
                sa = fmaf(dre, cA[m], fmaf(dim, sA[m], sa));
                sb = fmaf(dre, cB[m], fmaf(dim, sB[m], sb));
            }
            sa = fmaxf(sa, 1e-30f);
            sb = fmaxf(sb, 1e-30f);
            lpA[ch] = sa * __frsqrt_rn(sa);
            lpB[ch] = sb * __frsqrt_rn(sb);
        }

        // output accumulators init with bias + residual
        float yA[3], yB[3];
#pragma unroll
        for (int ch = 0; ch < 3; ch++) {
            yA[ch] = B2r[ch] + lpA[ch];
            yB[ch] = B2r[ch] + lpB[ch];
        }
        // hidden units computed and immediately consumed (no hv arrays)
#pragma unroll
        for (int j = 0; j < 8; j++) {
            float aA = B1r[j], aB = B1r[j];
            aA = fmaf(W1r[j][0], lpA[0], aA);  aB = fmaf(W1r[j][0], lpB[0], aB);
            aA = fmaf(W1r[j][1], lpA[1], aA);  aB = fmaf(W1r[j][1], lpB[1], aB);
            aA = fmaf(W1r[j][2], lpA[2], aA);  aB = fmaf(W1r[j][2], lpB[2], aB);
            aA = fmaxf(aA, 0.f);               aB = fmaxf(aB, 0.f);
#pragma unroll
            for (int ch = 0; ch < 3; ch++) {
                yA[ch] = fmaf(W2r[ch][j], aA, yA[ch]);
                yB[ch] = fmaf(W2r[ch][j], aB, yB[ch]);
            }
        }

#pragma unroll
        for (int ch = 0; ch < 3; ch++) {
            float2 yv;
            yv.x = __saturatef(yA[ch]);
            yv.y = __saturatef(yB[ch]);
            float2* orow = (float2*)(out + (((size_t)(b * 3 + ch) * HH) + (h0 + r)) * WW);
            orow[t] = yv;
        }
    }
}

// ---------------------------------------------------------------------------
extern "C" void kernel_launch(void* const* d_in, const int* in_sizes, int n_in,
                              void* d_out, int out_size) {
    const float* x  = (const float*)d_in[0];
    const float* w1 = (const float*)d_in[1];
    const float* b1 = (const float*)d_in[2];
    const float* w2 = (const float*)d_in[3];
    const float* b2 = (const float*)d_in[4];
    float* out = (float*)d_out;

    k1_coldft<<<dim3(NCHUNK, BB * CCH), 128>>>(x);
    k2a_project<<<dim3(BB * CCH, 7), 512>>>();
    k2b_reduce<<<BB * CCH, 512>>>();
    k3_final<<<dim3(HH / R3ROWS, BB), 256>>>(w1, b1, w2, b2, out);
}

// round 16
// speedup vs baseline: 1.4303x; 1.3870x over previous
#include <cuda_runtime.h>
#include <math.h>

#define HH 512
#define WW 512
#define BB 32
#define CCH 3
#define NK 6
#define NCHUNK 8
#define CROWS 64          // HH / NCHUNK
#define R3ROWS 8
#define TWO_PI 6.283185307179586f

typedef unsigned long long u64;

__device__ __forceinline__ u64 pk(float lo, float hi) {
    u64 r; asm("mov.b64 %0,{%1,%2};" : "=l"(r) : "f"(lo), "f"(hi)); return r;
}
__device__ __forceinline__ float2 upk(u64 v) {
    float2 f; asm("mov.b64 {%0,%1},%2;" : "=f"(f.x), "=f"(f.y) : "l"(v)); return f;
}
__device__ __forceinline__ u64 fma2_(u64 a, u64 b, u64 c) {
    u64 d; asm("fma.rn.f32x2 %0,%1,%2,%3;" : "=l"(d) : "l"(a), "l"(b), "l"(c)); return d;
}
__device__ __forceinline__ u64 add2_(u64 a, u64 b) {
    u64 d; asm("add.rn.f32x2 %0,%1,%2;" : "=l"(d) : "l"(a), "l"(b)); return d;
}
__device__ __forceinline__ float sqrt_ap(float x) {
    float y; asm("sqrt.approx.f32 %0,%1;" : "=f"(y) : "f"(x)); return y;
}

// Scratch (device globals — no allocation allowed)
__device__ float  g_Fpart[BB * CCH * NCHUNK * 72];  // [bc][chunk][u*6+k][re,im]
__device__ float4 g_d4[BB * CCH * HH * 3];          // [bc][h][12]: autocorr coeffs

// ---------------------------------------------------------------------------
// Kernel 1 (R12 measured 27.4us): partial F[u][k] over a 64-row tile.
// Real-input symmetry: 7 accumulators, 3 complex twiddles per row.
// Thread = float4 of w. Block 128, grid (8, 96) = 768 blocks.
// ---------------------------------------------------------------------------
__global__ __launch_bounds__(128) void k1_coldft(const float* __restrict__ x) {
    const int chunk = blockIdx.x;
    const int bc    = blockIdx.y;
    const int t     = threadIdx.x;
    const int h0    = chunk * CROWS;

    __shared__ __align__(16) u64 twc[CROWS][3], tws[CROWS][3];
    __shared__ float sm_part[4][72];

    for (int i = t; i < CROWS * 3; i += 128) {
        int hl = i / 3, K = (i % 3) + 1;
        float a = TWO_PI * (float)(h0 + hl) * (1.0f / (float)HH) * (float)K;
        float s, c; __sincosf(a, &s, &c);
        twc[hl][K - 1] = pk(c, c);
        tws[hl][K - 1] = pk(s, s);
    }
    __syncthreads();

    u64 S0[2] = {0ULL, 0ULL};
    u64 Cr[3][2], Ci[3][2];
#pragma unroll
    for (int K = 0; K < 3; K++) { Cr[K][0] = Cr[K][1] = 0ULL; Ci[K][0] = Ci[K][1] = 0ULL; }

    const float4* xp = (const float4*)(x + (size_t)bc * HH * WW + (size_t)h0 * WW) + t;
#pragma unroll 8
    for (int hl = 0; hl < CROWS; ++hl) {
        float4 v = __ldg(xp + (size_t)hl * (WW / 4));
        u64 v01 = pk(v.x, v.y), v23 = pk(v.z, v.w);
        S0[0] = add2_(S0[0], v01);
        S0[1] = add2_(S0[1], v23);
#pragma unroll
        for (int K = 0; K < 3; K++) {
            u64 cc = twc[hl][K], ss = tws[hl][K];
            Cr[K][0] = fma2_(v01, cc, Cr[K][0]);
            Ci[K][0] = fma2_(v01, ss, Ci[K][0]);
            Cr[K][1] = fma2_(v23, cc, Cr[K][1]);
            Ci[K][1] = fma2_(v23, ss, Ci[K][1]);
        }
    }

    float cre[6][4], cim[6][4];
    {
        float2 a0 = upk(S0[0]), a1 = upk(S0[1]);
        cre[3][0] = a0.x; cre[3][1] = a0.y; cre[3][2] = a1.x; cre[3][3] = a1.y;
        cim[3][0] = cim[3][1] = cim[3][2] = cim[3][3] = 0.f;
#pragma unroll
        for (int K = 1; K <= 3; K++) {
            float2 r0 = upk(Cr[K - 1][0]), r1 = upk(Cr[K - 1][1]);
            float2 i0 = upk(Ci[K - 1][0]), i1 = upk(Ci[K - 1][1]);
            float rv[4] = { r0.x, r0.y, r1.x, r1.y };
            float iv[4] = { i0.x, i0.y, i1.x, i1.y };
            int um = 3 - K, up = 3 + K;
#pragma unroll
            for (int j = 0; j < 4; j++) {
                cre[um][j] = rv[j]; cim[um][j] = iv[j];
                if (up < 6) { cre[up][j] = rv[j]; cim[up][j] = -iv[j]; }
            }
        }
    }

    float Ec[4][6], Es[4][6];
#pragma unroll
    for (int j = 0; j < 4; j++) {
        float phi = TWO_PI * (float)(4 * t + j) * (1.0f / (float)WW);
        float c1, s1; __sincosf(phi, &s1, &c1);
        float c2 = c1 * c1 - s1 * s1, s2 = 2.f * c1 * s1;
        float c3 = c2 * c1 - s2 * s1, s3 = c2 * s1 + s2 * c1;
        Ec[j][0] = c3; Es[j][0] = s3;
        Ec[j][1] = c2; Es[j][1] = s2;
        Ec[j][2] = c1; Es[j][2] = s1;
        Ec[j][3] = 1.f; Es[j][3] = 0.f;
        Ec[j][4] = c1; Es[j][4] = -s1;
        Ec[j][5] = c2; Es[j][5] = -s2;
    }

    const int wid = t >> 5, lid = t & 31;
#pragma unroll
    for (int u = 0; u < 6; u++) {
        float fr[6], fi[6];
#pragma unroll
        for (int k = 0; k < 6; k++) { fr[k] = 0.f; fi[k] = 0.f; }
#pragma unroll
        for (int j = 0; j < 4; j++) {
            float gr = cre[u][j], gi = cim[u][j];
#pragma unroll
            for (int k = 0; k < 6; k++) {
                fr[k] = fmaf(gr, Ec[j][k], fmaf(-gi, Es[j][k], fr[k]));
                fi[k] = fmaf(gr, Es[j][k], fmaf( gi, Ec[j][k], fi[k]));
            }
        }
#pragma unroll
        for (int off = 16; off >= 1; off >>= 1) {
#pragma unroll
            for (int k = 0; k < 6; k++) {
                fr[k] += __shfl_xor_sync(0xFFFFFFFFu, fr[k], off);
                fi[k] += __shfl_xor_sync(0xFFFFFFFFu, fi[k], off);
            }
        }
        if (lid == 0) {
#pragma unroll
            for (int k = 0; k < 6; k++) {
                sm_part[wid][(u * 6 + k) * 2 + 0] = fr[k];
                sm_part[wid][(u * 6 + k) * 2 + 1] = fi[k];
            }
        }
    }
    __syncthreads();

    if (t < 72) {
        float s = sm_part[0][t] + sm_part[1][t] + sm_part[2][t] + sm_part[3][t];
        g_Fpart[((size_t)bc * NCHUNK + chunk) * 72 + t] = s;
    }
}

// ---------------------------------------------------------------------------
// Kernel 2 (R12, ~4.5us): sum chunk partials -> F; gg; autocorr -> g_d4.
// grid 96, block 512.
// ---------------------------------------------------------------------------
__global__ __launch_bounds__(512) void k2_reduce() {
    const int bc = blockIdx.x;
    const int t  = threadIdx.x;

    __shared__ float F[72];

    if (t < 72) {
        const float* fp = g_Fpart + (size_t)bc * NCHUNK * 72 + t;
        float s = 0.f;
#pragma unroll
        for (int c = 0; c < NCHUNK; c++) s += fp[c * 72];
        F[t] = s * (1.0f / ((float)HH * (float)WW));
    }
    __syncthreads();

    {
        float psi = TWO_PI * (float)t * (1.0f / (float)HH);
        float d1c, d1s; __sincosf(psi, &d1s, &d1c);
        float d2c = d1c * d1c - d1s * d1s, d2s = 2.f * d1c * d1s;
        float d3c = d2c * d1c - d2s * d1s, d3s = d2c * d1s + d2s * d1c;
        float Dc[6] = { d3c,  d2c,  d1c,  1.f, d1c, d2c };
        float Ds[6] = { -d3s, -d2s, -d1s, 0.f, d1s, d2s };

        float gr[6], gi[6];
#pragma unroll
        for (int k = 0; k < 6; k++) {
            float r = 0.f, im = 0.f;
#pragma unroll
            for (int u = 0; u < 6; u++) {
                float Fr = F[(u * 6 + k) * 2 + 0];
                float Fi = F[(u * 6 + k) * 2 + 1];
                r  += Fr * Dc[u] - Fi * Ds[u];
                im += Fr * Ds[u] + Fi * Dc[u];
            }
            gr[k] = r; gi[k] = im;
        }

        // autocorr: |z|^2 = d0 + sum_m d[2m-1] cos(m phi) + d[2m] sin(m phi)
        float d[12];
        {
            float c0 = 0.f;
#pragma unroll
            for (int k = 0; k < 6; k++) c0 = fmaf(gr[k], gr[k], fmaf(gi[k], gi[k], c0));
            d[0] = c0;
#pragma unroll
            for (int m = 1; m <= 5; m++) {
                float re = 0.f, im = 0.f;
#pragma unroll
                for (int k = m; k < 6; k++) {
                    re = fmaf(gr[k], gr[k - m], fmaf(gi[k], gi[k - m], re));
                    im = fmaf(gi[k], gr[k - m], fmaf(-gr[k], gi[k - m], im));
                }
                d[2 * m - 1] = 2.f * re;
                d[2 * m]     = -2.f * im;
            }
            d[11] = 0.f;
        }

        float4* dp = g_d4 + ((size_t)bc * HH + t) * 3;
        dp[0] = make_float4(d[0], d[1], d[2],  d[3]);
        dp[1] = make_float4(d[4], d[5], d[6],  d[7]);
        dp[2] = make_float4(d[8], d[9], d[10], d[11]);
    }
}

// ---------------------------------------------------------------------------
// Kernel 3: autocorr recon (float4 LDS, sqrt.approx) + fused MLP + clip.
// 2 pixels per thread; output accumulation interleaved (no hv arrays).
// grid (H/8, B) = (64, 32), block 256, __launch_bounds__(256,3).
// ---------------------------------------------------------------------------
__global__ __launch_bounds__(256, 3) void k3_final(const float* __restrict__ w1,
                                                   const float* __restrict__ b1,
                                                   const float* __restrict__ w2,
                                                   const float* __restrict__ b2,
                                                   float* __restrict__ out) {
    const int b  = blockIdx.y;
    const int h0 = blockIdx.x * R3ROWS;
    const int t  = threadIdx.x;   // pixel pair (2t, 2t+1)

    __shared__ __align__(16) float4 sd4[R3ROWS * 3 * 3];  // [r][ch][3 float4]
    __shared__ float wt[64];

    if (t < 72) {
        int r  = t / 9;
        int ch = (t % 9) / 3;
        int q  = t % 3;
        sd4[(r * 3 + ch) * 3 + q] = g_d4[(((size_t)(b * 3 + ch) * HH) + (h0 + r)) * 3 + q];
    } else if (t >= 128 && t < 128 + 24) {
        wt[t - 128] = w1[t - 128];
    } else if (t >= 128 + 24 && t < 128 + 32) {
        wt[t - 128] = b1[t - 152];
    } else if (t >= 128 + 32 && t < 128 + 56) {
        wt[t - 128] = w2[t - 160];
    } else if (t >= 128 + 56 && t < 128 + 59) {
        wt[t - 128] = b2[t - 184];
    }
    __syncthreads();

    float W1r[8][3], B1r[8], W2r[3][8], B2r[3];
#pragma unroll
    for (int j = 0; j < 8; j++) {
#pragma unroll
        for (int cc = 0; cc < 3; cc++) W1r[j][cc] = wt[j * 3 + cc];
        B1r[j] = wt[24 + j];
    }
#pragma unroll
    for (int cc = 0; cc < 3; cc++) {
#pragma unroll
        for (int j = 0; j < 8; j++) W2r[cc][j] = wt[32 + cc * 8 + j];
        B2r[cc] = wt[56 + cc];
    }

    // cos/sin basis m=1..5, both pixels (Chebyshev, hoisted)
    float cA[6], sA[6], cB[6], sB[6];
    {
        const int w0 = 2 * t;
        __sincosf(TWO_PI * (float)w0       * (1.0f / (float)WW), &sA[1], &cA[1]);
        __sincosf(TWO_PI * (float)(w0 + 1) * (1.0f / (float)WW), &sB[1], &cB[1]);
        float kA = 2.f * cA[1], kB = 2.f * cB[1];
        cA[0] = 1.f; sA[0] = 0.f; cB[0] = 1.f; sB[0] = 0.f;
#pragma unroll
        for (int m = 2; m <= 5; m++) {
            cA[m] = fmaf(kA, cA[m - 1], -cA[m - 2]);
            sA[m] = fmaf(kA, sA[m - 1], -sA[m - 2]);
            cB[m] = fmaf(kB, cB[m - 1], -cB[m - 2]);
            sB[m] = fmaf(kB, sB[m - 1], -sB[m - 2]);
        }
    }

    const float4* sp = sd4;
#pragma unroll
    for (int r = 0; r < R3ROWS; ++r) {
        float lpA[3], lpB[3];
#pragma unroll
        for (int ch = 0; ch < 3; ch++) {
            float4 q0 = sp[0], q1 = sp[1], q2 = sp[2];
            sp += 3;
            // layout: q0=(d0, c1, s1, c2) q1=(s2, c3, s3, c4) q2=(s4, c5, s5, 0)
            float sa = q0.x, sb = q0.x;
            sa = fmaf(q0.y, cA[1], sa);  sb = fmaf(q0.y, cB[1], sb);
            sa = fmaf(q0.z, sA[1], sa);  sb = fmaf(q0.z, sB[1], sb);
            sa = fmaf(q0.w, cA[2], sa);  sb = fmaf(q0.w, cB[2], sb);
            sa = fmaf(q1.x, sA[2], sa);  sb = fmaf(q1.x, sB[2], sb);
            sa = fmaf(q1.y, cA[3], sa);  sb = fmaf(q1.y, cB[3], sb);
            sa = fmaf(q1.z, sA[3], sa);  sb = fmaf(q1.z, sB[3], sb);
            sa = fmaf(q1.w, cA[4], sa);  sb = fmaf(q1.w, cB[4], sb);
            sa = fmaf(q2.x, sA[4], sa);  sb = fmaf(q2.x, sB[4], sb);
            sa = fmaf(q2.y, cA[5], sa);  sb = fmaf(q2.y, cB[5], sb);
            sa = fmaf(q2.z, sA[5], sa);  sb = fmaf(q2.z, sB[5], sb);
            lpA[ch] = sqrt_ap(fmaxf(sa, 0.f));
            lpB[ch] = sqrt_ap(fmaxf(sb, 0.f));
        }

        float yA[3], yB[3];
#pragma unroll
        for (int ch = 0; ch < 3; ch++) {
            yA[ch] = B2r[ch] + lpA[ch];
            yB[ch] = B2r[ch] + lpB[ch];
        }
#pragma unroll
        for (int j = 0; j < 8; j++) {
            float aA = B1r[j], aB = B1r[j];
            aA = fmaf(W1r[j][0], lpA[0], aA);  aB = fmaf(W1r[j][0], lpB[0], aB);
            aA = fmaf(W1r[j][1], lpA[1], aA);  aB = fmaf(W1r[j][1], lpB[1], aB);
            aA = fmaf(W1r[j][2], lpA[2], aA);  aB = fmaf(W1r[j][2], lpB[2], aB);
            aA = fmaxf(aA, 0.f);               aB = fmaxf(aB, 0.f);
#pragma unroll
            for (int ch = 0; ch < 3; ch++) {
                yA[ch] = fmaf(W2r[ch][j], aA, yA[ch]);
                yB[ch] = fmaf(W2r[ch][j], aB, yB[ch]);
            }
        }

        float2* orow0 = (float2*)(out + (((size_t)(b * 3) * HH) + (h0 + r)) * WW) + t;
#pragma unroll
        for (int ch = 0; ch < 3; ch++) {
            float2 yv;
            yv.x = __saturatef(yA[ch]);
            yv.y = __saturatef(yB[ch]);
            orow0[(size_t)ch * HH * (WW / 2)] = yv;
        }
    }
}

// ---------------------------------------------------------------------------
extern "C" void kernel_launch(void* const* d_in, const int* in_sizes, int n_in,
                              void* d_out, int out_size) {
    const float* x  = (const float*)d_in[0];
    const float* w1 = (const float*)d_in[1];
    const float* b1 = (const float*)d_in[2];
    const float* w2 = (const float*)d_in[3];
    const float* b2 = (const float*)d_in[4];
    float* out = (float*)d_out;

    k1_coldft<<<dim3(NCHUNK, BB * CCH), 128>>>(x);
    k2_reduce<<<BB * CCH, 512>>>();
    k3_final<<<dim3(HH / R3ROWS, BB), 256>>>(w1, b1, w2, b2, out);
}